// round 4
// baseline (speedup 1.0000x reference)
#include <cuda_runtime.h>
#include <stdint.h>

// Problem constants (fixed by the dataset)
#define N_NODES 50000
#define IN_DIM  128
#define N_EDGES 500000   // divisible by 4 -> no tail in the vectorized edge kernel

// Scratch: per-node projections. [0:N_NODES) = proj_src, [N_NODES:2N) = proj_dst.
__device__ float g_proj[2 * N_NODES];

// ---------------------------------------------------------------------------
// Kernel 1: node projection. One warp per node.
// Each lane loads one float4 of the 128-float row (warp reads exactly the
// 512B row, fully coalesced) plus the matching float4 of each weight half.
// Two dot-products accumulated simultaneously, butterfly-reduced.
// ---------------------------------------------------------------------------
__global__ __launch_bounds__(256) void proj_kernel(const float* __restrict__ x,
                                                   const float* __restrict__ W) {
    const int warp_id = (blockIdx.x * blockDim.x + threadIdx.x) >> 5;
    const int lane    = threadIdx.x & 31;
    if (warp_id >= N_NODES) return;

    const float4 xv = reinterpret_cast<const float4*>(x + (size_t)warp_id * IN_DIM)[lane];
    const float4 wa = reinterpret_cast<const float4*>(W)[lane];            // W[:128]
    const float4 wb = reinterpret_cast<const float4*>(W + IN_DIM)[lane];   // W[128:]

    float sa = xv.x * wa.x + xv.y * wa.y + xv.z * wa.z + xv.w * wa.w;
    float sb = xv.x * wb.x + xv.y * wb.y + xv.z * wb.z + xv.w * wb.w;

    #pragma unroll
    for (int off = 16; off > 0; off >>= 1) {
        sa += __shfl_xor_sync(0xFFFFFFFFu, sa, off);
        sb += __shfl_xor_sync(0xFFFFFFFFu, sb, off);
    }

    if (lane == 0) {
        g_proj[warp_id]           = sa;
        g_proj[N_NODES + warp_id] = sb;
    }
}

// ---------------------------------------------------------------------------
// Kernel 2: per-edge gather + sigmoid + scale. FOUR edges per thread with
// vectorized (128-bit) loads for both index rows, edge_weight, and out.
// edge_index is [2, E]; JAX with default x64-disabled emits it as INT32,
// despite the reference asking for int64. src = idx[e], dst = idx[E + e].
// The 8 gathers/thread hit the 400KB proj arrays (fully L2-resident), MLP=8
// hides the ~234cyc L2 latency.
// ---------------------------------------------------------------------------
__device__ __forceinline__ float sigmoid_fast(float v) {
    return 1.0f / (1.0f + __expf(-v));   // |rel err| ~1e-6, budget is 1e-3
}

__global__ __launch_bounds__(256) void edge_kernel(const int* __restrict__ edge_index,
                                                   const float* __restrict__ edge_weight,
                                                   const float* __restrict__ b,
                                                   float* __restrict__ out) {
    const int t = blockIdx.x * blockDim.x + threadIdx.x;   // 0 .. E/4-1
    if (t >= N_EDGES / 4) return;

    const int4   sv = reinterpret_cast<const int4*>(edge_index)[t];
    const int4   dv = reinterpret_cast<const int4*>(edge_index + N_EDGES)[t];
    const float4 wv = reinterpret_cast<const float4*>(edge_weight)[t];
    const float  bias = b[0];

    // Defensive clamp: wrong-dtype theory -> clean rel_err failure, not a fault.
    const int s0 = min(max(sv.x, 0), N_NODES - 1), s1 = min(max(sv.y, 0), N_NODES - 1);
    const int s2 = min(max(sv.z, 0), N_NODES - 1), s3 = min(max(sv.w, 0), N_NODES - 1);
    const int d0 = min(max(dv.x, 0), N_NODES - 1), d1 = min(max(dv.y, 0), N_NODES - 1);
    const int d2 = min(max(dv.z, 0), N_NODES - 1), d3 = min(max(dv.w, 0), N_NODES - 1);

    // 8 independent L2-resident gathers
    const float ps0 = g_proj[s0], ps1 = g_proj[s1], ps2 = g_proj[s2], ps3 = g_proj[s3];
    const float pd0 = g_proj[N_NODES + d0], pd1 = g_proj[N_NODES + d1];
    const float pd2 = g_proj[N_NODES + d2], pd3 = g_proj[N_NODES + d3];

    float4 r;
    r.x = wv.x * sigmoid_fast(ps0 + pd0 + bias);
    r.y = wv.y * sigmoid_fast(ps1 + pd1 + bias);
    r.z = wv.z * sigmoid_fast(ps2 + pd2 + bias);
    r.w = wv.w * sigmoid_fast(ps3 + pd3 + bias);

    reinterpret_cast<float4*>(out)[t] = r;
}

// ---------------------------------------------------------------------------
// Launch. Inputs (metadata order): x, edge_index, edge_weight, W, b.
// ---------------------------------------------------------------------------
extern "C" void kernel_launch(void* const* d_in, const int* in_sizes, int n_in,
                              void* d_out, int out_size) {
    const float* x  = (const float*)d_in[0];
    const int*   ei = (const int*)d_in[1];
    const float* ew = (const float*)d_in[2];
    const float* W  = (const float*)d_in[3];
    const float* b  = (const float*)d_in[4];
    float*       o  = (float*)d_out;

    // Kernel 1: one warp per node -> 50000 warps
    {
        const int threads = 256;
        const int warps_per_block = threads / 32;
        const int blocks = (N_NODES + warps_per_block - 1) / warps_per_block;
        proj_kernel<<<blocks, threads>>>(x, W);
    }
    // Kernel 2: four edges per thread -> E/4 threads
    {
        const int threads = 256;
        const int work    = N_EDGES / 4;
        const int blocks  = (work + threads - 1) / threads;
        edge_kernel<<<blocks, threads>>>(ei, ew, b, o);
    }
}

// round 5
// speedup vs baseline: 1.1537x; 1.1537x over previous
#include <cuda_runtime.h>
#include <stdint.h>

// Problem constants (fixed by the dataset)
#define N_NODES 50000    // divisible by 4 -> clean 4-nodes-per-warp proj
#define IN_DIM  128
#define N_EDGES 500000   // divisible by 2 -> no tail in the edge kernel

// Scratch: per-node projections. [0:N_NODES) = proj_src, [N_NODES:2N) = proj_dst.
__device__ float g_proj[2 * N_NODES];

// ---------------------------------------------------------------------------
// Kernel 1: node projection. FOUR nodes per warp for MLP=4 on the x stream.
// Each lane loads one float4 of each of the 4 rows (4 independent LDG.128,
// each warp-coalesced to a full 512B row), plus the two weight halves
// (L1-hot after the first block on each SM). Results are written as two
// coalesced STG.128 (float4) stores by lane 0.
// ---------------------------------------------------------------------------
__global__ __launch_bounds__(256) void proj_kernel(const float* __restrict__ x,
                                                   const float* __restrict__ W) {
    const int warp_id = (blockIdx.x * blockDim.x + threadIdx.x) >> 5;
    const int lane    = threadIdx.x & 31;
    const int base    = warp_id * 4;           // first node of this warp's group
    if (base >= N_NODES) return;

    const float4 wa = reinterpret_cast<const float4*>(W)[lane];            // W[:128]
    const float4 wb = reinterpret_cast<const float4*>(W + IN_DIM)[lane];   // W[128:]

    // 4 independent row loads -> 4 outstanding DRAM streams per warp
    float4 xv[4];
    #pragma unroll
    for (int i = 0; i < 4; i++)
        xv[i] = reinterpret_cast<const float4*>(x + (size_t)(base + i) * IN_DIM)[lane];

    float sa[4], sb[4];
    #pragma unroll
    for (int i = 0; i < 4; i++) {
        sa[i] = xv[i].x * wa.x + xv[i].y * wa.y + xv[i].z * wa.z + xv[i].w * wa.w;
        sb[i] = xv[i].x * wb.x + xv[i].y * wb.y + xv[i].z * wb.z + xv[i].w * wb.w;
    }

    #pragma unroll
    for (int off = 16; off > 0; off >>= 1) {
        #pragma unroll
        for (int i = 0; i < 4; i++) {
            sa[i] += __shfl_xor_sync(0xFFFFFFFFu, sa[i], off);
            sb[i] += __shfl_xor_sync(0xFFFFFFFFu, sb[i], off);
        }
    }

    if (lane == 0) {
        // base is a multiple of 4 and N_NODES % 4 == 0 -> both stores 16B-aligned
        *reinterpret_cast<float4*>(g_proj + base) =
            make_float4(sa[0], sa[1], sa[2], sa[3]);
        *reinterpret_cast<float4*>(g_proj + N_NODES + base) =
            make_float4(sb[0], sb[1], sb[2], sb[3]);
    }
}

// ---------------------------------------------------------------------------
// Kernel 2: per-edge gather + sigmoid + scale. TWO edges per thread
// (250K threads) -> double the resident warps vs 4/thread while keeping
// total in-flight gathers constant; tests the latency-limited hypothesis.
// edge_index is [2, E] int32 (JAX x64-disabled). Gathers hit the 400KB
// proj arrays (L2-resident, partially L1-resident).
// ---------------------------------------------------------------------------
__device__ __forceinline__ float sigmoid_fast(float v) {
    return 1.0f / (1.0f + __expf(-v));   // |rel err| ~1e-6, budget is 1e-3
}

__global__ __launch_bounds__(256) void edge_kernel(const int* __restrict__ edge_index,
                                                   const float* __restrict__ edge_weight,
                                                   const float* __restrict__ b,
                                                   float* __restrict__ out) {
    const int t = blockIdx.x * blockDim.x + threadIdx.x;   // 0 .. E/2-1
    if (t >= N_EDGES / 2) return;

    const int2   sv = reinterpret_cast<const int2*>(edge_index)[t];
    const int2   dv = reinterpret_cast<const int2*>(edge_index + N_EDGES)[t];
    const float2 wv = reinterpret_cast<const float2*>(edge_weight)[t];
    const float  bias = b[0];

    // Defensive clamp (free vs memory latency; wrong dtype -> rel_err, not fault)
    const int s0 = min(max(sv.x, 0), N_NODES - 1), s1 = min(max(sv.y, 0), N_NODES - 1);
    const int d0 = min(max(dv.x, 0), N_NODES - 1), d1 = min(max(dv.y, 0), N_NODES - 1);

    // 4 independent gathers
    const float ps0 = g_proj[s0], ps1 = g_proj[s1];
    const float pd0 = g_proj[N_NODES + d0], pd1 = g_proj[N_NODES + d1];

    float2 r;
    r.x = wv.x * sigmoid_fast(ps0 + pd0 + bias);
    r.y = wv.y * sigmoid_fast(ps1 + pd1 + bias);
    reinterpret_cast<float2*>(out)[t] = r;
}

// ---------------------------------------------------------------------------
// Launch. Inputs (metadata order): x, edge_index, edge_weight, W, b.
// ---------------------------------------------------------------------------
extern "C" void kernel_launch(void* const* d_in, const int* in_sizes, int n_in,
                              void* d_out, int out_size) {
    const float* x  = (const float*)d_in[0];
    const int*   ei = (const int*)d_in[1];
    const float* ew = (const float*)d_in[2];
    const float* W  = (const float*)d_in[3];
    const float* b  = (const float*)d_in[4];
    float*       o  = (float*)d_out;

    // Kernel 1: four nodes per warp -> 12500 warps
    {
        const int threads = 256;
        const int warps_per_block = threads / 32;
        const int node_groups = N_NODES / 4;                 // 12500
        const int blocks = (node_groups + warps_per_block - 1) / warps_per_block;
        proj_kernel<<<blocks, threads>>>(x, W);
    }
    // Kernel 2: two edges per thread -> E/2 threads
    {
        const int threads = 256;
        const int work    = N_EDGES / 2;
        const int blocks  = (work + threads - 1) / threads;
        edge_kernel<<<blocks, threads>>>(ei, ew, b, o);
    }
}

// round 6
// speedup vs baseline: 1.1562x; 1.0022x over previous
#include <cuda_runtime.h>
#include <stdint.h>

// Problem constants (fixed by the dataset)
#define N_NODES 50000    // divisible by 8 -> clean 8-nodes-per-warp proj
#define IN_DIM  128
#define N_EDGES 500000   // divisible by 2 -> no tail in the edge kernel

// Scratch: per-node projections. [0:N_NODES) = proj_src, [N_NODES:2N) = proj_dst.
__device__ float g_proj[2 * N_NODES];

// ---------------------------------------------------------------------------
// Kernel 1: node projection. EIGHT nodes per warp -> 8 independent LDG.128
// streams per warp (MLP=8) to saturate DRAM. Weight halves are L1-hot.
// Results written as 2x float4 coalesced stores by lane 0.
// ---------------------------------------------------------------------------
__global__ __launch_bounds__(256) void proj_kernel(const float* __restrict__ x,
                                                   const float* __restrict__ W) {
    const int warp_id = (blockIdx.x * blockDim.x + threadIdx.x) >> 5;
    const int lane    = threadIdx.x & 31;
    const int base    = warp_id * 8;           // first node of this warp's group
    if (base >= N_NODES) return;

    const float4 wa = reinterpret_cast<const float4*>(W)[lane];            // W[:128]
    const float4 wb = reinterpret_cast<const float4*>(W + IN_DIM)[lane];   // W[128:]

    // 8 independent row loads -> 8 outstanding DRAM streams per warp
    float4 xv[8];
    #pragma unroll
    for (int i = 0; i < 8; i++)
        xv[i] = reinterpret_cast<const float4*>(x + (size_t)(base + i) * IN_DIM)[lane];

    float sa[8], sb[8];
    #pragma unroll
    for (int i = 0; i < 8; i++) {
        sa[i] = xv[i].x * wa.x + xv[i].y * wa.y + xv[i].z * wa.z + xv[i].w * wa.w;
        sb[i] = xv[i].x * wb.x + xv[i].y * wb.y + xv[i].z * wb.z + xv[i].w * wb.w;
    }

    #pragma unroll
    for (int off = 16; off > 0; off >>= 1) {
        #pragma unroll
        for (int i = 0; i < 8; i++) {
            sa[i] += __shfl_xor_sync(0xFFFFFFFFu, sa[i], off);
            sb[i] += __shfl_xor_sync(0xFFFFFFFFu, sb[i], off);
        }
    }

    if (lane == 0) {
        // base is a multiple of 8, N_NODES % 8 == 0 -> all stores 16B-aligned
        *reinterpret_cast<float4*>(g_proj + base) =
            make_float4(sa[0], sa[1], sa[2], sa[3]);
        *reinterpret_cast<float4*>(g_proj + base + 4) =
            make_float4(sa[4], sa[5], sa[6], sa[7]);
        *reinterpret_cast<float4*>(g_proj + N_NODES + base) =
            make_float4(sb[0], sb[1], sb[2], sb[3]);
        *reinterpret_cast<float4*>(g_proj + N_NODES + base + 4) =
            make_float4(sb[4], sb[5], sb[6], sb[7]);
    }
}

// ---------------------------------------------------------------------------
// Sigmoid with ONE MUFU op (tanh.approx) instead of two (EX2 + RCP):
//   sigmoid(x) = 0.5 * tanh(x/2) + 0.5      (approx err ~1e-5, budget 1e-3)
// This halves MUFU-pipe pressure, the suspected edge-kernel floor.
// ---------------------------------------------------------------------------
__device__ __forceinline__ float sigmoid_tanh(float v) {
    float t;
    asm("tanh.approx.f32 %0, %1;" : "=f"(t) : "f"(0.5f * v));
    return fmaf(0.5f, t, 0.5f);
}

// ---------------------------------------------------------------------------
// Kernel 2: per-edge gather + sigmoid + scale. Two edges per thread
// (250K threads, 63% occ measured). edge_index is [2, E] int32
// (JAX x64-disabled). Gathers hit the 400KB proj arrays (L2-resident).
// ---------------------------------------------------------------------------
__global__ __launch_bounds__(256) void edge_kernel(const int* __restrict__ edge_index,
                                                   const float* __restrict__ edge_weight,
                                                   const float* __restrict__ b,
                                                   float* __restrict__ out) {
    const int t = blockIdx.x * blockDim.x + threadIdx.x;   // 0 .. E/2-1
    if (t >= N_EDGES / 2) return;

    const int2   sv = reinterpret_cast<const int2*>(edge_index)[t];
    const int2   dv = reinterpret_cast<const int2*>(edge_index + N_EDGES)[t];
    const float2 wv = reinterpret_cast<const float2*>(edge_weight)[t];
    const float  bias = b[0];

    // Defensive clamp (free vs memory latency; wrong dtype -> rel_err, not fault)
    const int s0 = min(max(sv.x, 0), N_NODES - 1), s1 = min(max(sv.y, 0), N_NODES - 1);
    const int d0 = min(max(dv.x, 0), N_NODES - 1), d1 = min(max(dv.y, 0), N_NODES - 1);

    // 4 independent gathers
    const float ps0 = g_proj[s0], ps1 = g_proj[s1];
    const float pd0 = g_proj[N_NODES + d0], pd1 = g_proj[N_NODES + d1];

    float2 r;
    r.x = wv.x * sigmoid_tanh(ps0 + pd0 + bias);
    r.y = wv.y * sigmoid_tanh(ps1 + pd1 + bias);
    reinterpret_cast<float2*>(out)[t] = r;
}

// ---------------------------------------------------------------------------
// Launch. Inputs (metadata order): x, edge_index, edge_weight, W, b.
// ---------------------------------------------------------------------------
extern "C" void kernel_launch(void* const* d_in, const int* in_sizes, int n_in,
                              void* d_out, int out_size) {
    const float* x  = (const float*)d_in[0];
    const int*   ei = (const int*)d_in[1];
    const float* ew = (const float*)d_in[2];
    const float* W  = (const float*)d_in[3];
    const float* b  = (const float*)d_in[4];
    float*       o  = (float*)d_out;

    // Kernel 1: eight nodes per warp -> 6250 warps
    {
        const int threads = 256;
        const int warps_per_block = threads / 32;
        const int node_groups = N_NODES / 8;                 // 6250
        const int blocks = (node_groups + warps_per_block - 1) / warps_per_block;
        proj_kernel<<<blocks, threads>>>(x, W);
    }
    // Kernel 2: two edges per thread -> E/2 threads
    {
        const int threads = 256;
        const int work    = N_EDGES / 2;
        const int blocks  = (work + threads - 1) / threads;
        edge_kernel<<<blocks, threads>>>(ei, ew, b, o);
    }
}